// round 14
// baseline (speedup 1.0000x reference)
#include <cuda_runtime.h>
#include <cuda_fp16.h>
#include <math.h>
#include <stdint.h>

#define NN 100000
#define EE 1600000
#define INF 128
#define HID 256
#define GCO 256
#define FO  256

// ---- fp16 mma.sync GEMM tile config ----------------------------------------
#define BM 128
#define BN 128
#define BK 64                        // K elements per tile (64 halves = 128B/row)
#define LDH 72                       // smem row stride in halves (144B)
#define TILE_B (128 * LDH * 2)       // 18432 bytes (A or B tile)
#define NSTAGE 2
#define GEMM_SMEM (NSTAGE * 2 * TILE_B)   // 73728 bytes -> 3 CTAs/SM

__device__ __forceinline__ uint32_t smem_u32(const void* p) {
    uint32_t a;
    asm("{ .reg .u64 t; cvta.to.shared.u64 t, %1; cvt.u32.u64 %0, t; }"
        : "=r"(a) : "l"(p));
    return a;
}

__device__ __forceinline__ void cp16(uint32_t dst, const void* src, int sz) {
    asm volatile("cp.async.cg.shared.global [%0], [%1], 16, %2;"
                 :: "r"(dst), "l"(src), "r"(sz) : "memory");
}

__device__ __forceinline__ void mma_f16(float* d, const uint32_t* a,
                                        const uint32_t* b) {
    asm volatile(
        "mma.sync.aligned.m16n8k16.row.col.f32.f16.f16.f32 "
        "{%0,%1,%2,%3}, {%4,%5,%6,%7}, {%8,%9}, {%0,%1,%2,%3};"
        : "+f"(d[0]), "+f"(d[1]), "+f"(d[2]), "+f"(d[3])
        : "r"(a[0]), "r"(a[1]), "r"(a[2]), "r"(a[3]), "r"(b[0]), "r"(b[1]));
}

// ---------------------------------------------------------------------------
// Scratch (device globals: allocation-free)
__device__ __align__(16) __half g_feats_h[(size_t)NN * INF];
__device__ __align__(16) __half g_nfeats_h[(size_t)NN * HID];
__device__ __align__(16) __half g_xw_h[(size_t)NN * GCO];
__device__ __align__(16) __half g_gc_h[(size_t)NN * GCO];
__device__ __align__(16) __half g_W1T[HID * INF];
__device__ __align__(16) __half g_WgT[GCO * (HID + INF)];
__device__ __align__(16) __half g_WcT[FO * (HID + GCO)];
__device__ int   g_count[NN];
__device__ int   g_cursor[NN];
__device__ int   g_offsets[NN + 1];
__device__ float g_dinv[NN];
__device__ int   g_csr[EE];
__device__ int   g_bsum[512];
__device__ int   g_boff[512];
__device__ int   g_is64;

// ---------------------------------------------------------------------------
__global__ void detect_kernel(const unsigned int* __restrict__ ew, int nPairs) {
    __shared__ int nz;
    if (threadIdx.x == 0) nz = 0;
    __syncthreads();
    for (int i = threadIdx.x; i < nPairs; i += blockDim.x)
        if (ew[2 * i + 1] != 0u) { nz = 1; break; }
    __syncthreads();
    if (threadIdx.x == 0) g_is64 = (nz == 0) ? 1 : 0;
}

__device__ __forceinline__ long long ld_idx(const void* p, size_t i) {
    if (g_is64) return ((const long long*)p)[i];
    return (long long)((const int*)p)[i];
}

__global__ void zero_kernel(int n) {
    for (int i = blockIdx.x * blockDim.x + threadIdx.x; i < n;
         i += gridDim.x * blockDim.x) {
        g_count[i] = 0;
        g_cursor[i] = 0;
    }
}

__global__ void hist_kernel(const void* __restrict__ edges, int E) {
    for (int i = blockIdx.x * blockDim.x + threadIdx.x; i < E;
         i += gridDim.x * blockDim.x) {
        int d = (int)ld_idx(edges, (size_t)E + i);
        if (d >= 0 && d < NN) atomicAdd(&g_count[d], 1);
    }
}

__global__ void scan1_kernel(int n) {
    __shared__ int sh[256];
    int i = blockIdx.x * 256 + threadIdx.x;
    sh[threadIdx.x] = (i < n) ? g_count[i] : 0;
    __syncthreads();
    for (int off = 128; off > 0; off >>= 1) {
        if (threadIdx.x < off) sh[threadIdx.x] += sh[threadIdx.x + off];
        __syncthreads();
    }
    if (threadIdx.x == 0) g_bsum[blockIdx.x] = sh[0];
}

__global__ void scan2_kernel(int nb, int n) {
    __shared__ int sh[512];
    int t = threadIdx.x;
    int v = (t < nb) ? g_bsum[t] : 0;
    sh[t] = v;
    __syncthreads();
    for (int off = 1; off < 512; off <<= 1) {
        int x = (t >= off) ? sh[t - off] : 0;
        __syncthreads();
        sh[t] += x;
        __syncthreads();
    }
    if (t < nb) g_boff[t] = sh[t] - v;
    if (t == nb - 1) g_offsets[n] = sh[t];
}

__global__ void scan3_kernel(int n) {
    __shared__ int sh[256];
    int b = blockIdx.x, t = threadIdx.x;
    int i = b * 256 + t;
    int v = (i < n) ? g_count[i] : 0;
    sh[t] = v;
    __syncthreads();
    for (int off = 1; off < 256; off <<= 1) {
        int x = (t >= off) ? sh[t - off] : 0;
        __syncthreads();
        sh[t] += x;
        __syncthreads();
    }
    if (i < n) g_offsets[i] = sh[t] - v + g_boff[b];
}

__global__ void dinv_kernel(int n) {
    for (int i = blockIdx.x * blockDim.x + threadIdx.x; i < n;
         i += gridDim.x * blockDim.x)
        g_dinv[i] = rsqrtf((float)(g_count[i] + 1));
}

__global__ void scatter_kernel(const void* __restrict__ edges, int E) {
    for (int i = blockIdx.x * blockDim.x + threadIdx.x; i < E;
         i += gridDim.x * blockDim.x) {
        int s = (int)ld_idx(edges, i);
        int d = (int)ld_idx(edges, (size_t)E + i);
        if (s < 0 || s >= NN || d < 0 || d >= NN) continue;
        int pos = g_offsets[d] + atomicAdd(&g_cursor[d], 1);
        g_csr[pos] = s;
    }
}

// ---------------------------------------------------------------------------
// feats fp32 -> fp16 (rn)
__global__ void convert_feats_kernel(const float4* __restrict__ f4, int n4) {
    __half2* o2 = (__half2*)g_feats_h;
    for (int i = blockIdx.x * blockDim.x + threadIdx.x; i < n4;
         i += gridDim.x * blockDim.x) {
        float4 v = f4[i];
        o2[2 * i]     = __floats2half2_rn(v.x, v.y);
        o2[2 * i + 1] = __floats2half2_rn(v.z, v.w);
    }
}

// All 3 weight transposes fused: W[K,256] -> WT[256,K], fp16 (rn).
__global__ void transpose_all_kernel(const float* __restrict__ W1,
                                     const float* __restrict__ Wg,
                                     const float* __restrict__ Wc) {
    const int T1 = INF * 256;
    const int T2 = (HID + INF) * 256;
    const int T3 = (HID + GCO) * 256;
    int tot = T1 + T2 + T3;
    for (int i = blockIdx.x * blockDim.x + threadIdx.x; i < tot;
         i += gridDim.x * blockDim.x) {
        const float* W; __half* WT; int K, j;
        if (i < T1)           { W = W1; WT = g_W1T; K = INF;       j = i; }
        else if (i < T1 + T2) { W = Wg; WT = g_WgT; K = HID + INF; j = i - T1; }
        else                  { W = Wc; WT = g_WcT; K = HID + GCO; j = i - T1 - T2; }
        int k = j >> 8, n = j & 255;
        WT[(size_t)n * K + k] = __float2half_rn(W[(size_t)k * 256 + n]);
    }
}

// ---------------------------------------------------------------------------
// fp16 mma.sync GEMM: C[M,256] = concat_k(A1[M,K1], A2[M,K2]) @ WT^T
// BK=64 packed tiles (half the barriers), 2-stage cp.async, 3 CTAs/SM.
__global__ __launch_bounds__(256, 3) void tc_gemm(
    const __half* __restrict__ A1, int K1,
    const __half* __restrict__ A2, int K2,
    const __half* __restrict__ BT,
    const float* __restrict__ bias,
    void* __restrict__ Cv, int ldc, int M, int do_elu, int out_half)
{
    extern __shared__ char smem[];
    const uint32_t sb = smem_u32(smem);
    const int tid = threadIdx.x;
    const int wid = tid >> 5, lid = tid & 31;
    const int wm = wid >> 1, wn = wid & 1;
    const int m0 = blockIdx.y * BM;
    const int n0 = blockIdx.x * BN;
    const int Ktot = K1 + K2;
    const int nT = Ktot / BK;

    const int ldr = tid >> 1;           // 0..127 (tile row)
    const int ldh = (tid & 1) * 32;     // 0 or 32 halves (64B): row = 2x64B

    float acc[2][8][4];
#pragma unroll
    for (int i = 0; i < 2; i++)
#pragma unroll
        for (int j = 0; j < 8; j++)
#pragma unroll
            for (int q = 0; q < 4; q++) acc[i][j][q] = 0.f;

    auto load_stage = [&](int t) {
        const int s = t & 1;
        const uint32_t aOff = s * 2 * TILE_B;
        const uint32_t bOff = aOff + TILE_B;
        const int k0 = t * BK;
        const __half* A; int K, kc;
        if (k0 < K1) { A = A1; K = K1; kc = k0; }
        else         { A = A2; K = K2; kc = k0 - K1; }
        const int arow = m0 + ldr;
        const int asz = (arow < M) ? 16 : 0;
        const __half* asrc = A + (size_t)arow * K + kc + ldh;
        const __half* bsrc = BT + (size_t)(n0 + ldr) * Ktot + k0 + ldh;
        const uint32_t adst = sb + aOff + (ldr * LDH + ldh) * 2;
        const uint32_t bdst = sb + bOff + (ldr * LDH + ldh) * 2;
        // each thread covers 32 halves = 64B = 4x16B of its row
#pragma unroll
        for (int j = 0; j < 4; j++) {
            cp16(adst + j * 16, asrc + j * 8, asz);
            cp16(bdst + j * 16, bsrc + j * 8, 16);
        }
        asm volatile("cp.async.commit_group;" ::: "memory");
    };

    load_stage(0);

    for (int t = 0; t < nT; t++) {
        if (t + 1 < nT) {
            load_stage(t + 1);
            asm volatile("cp.async.wait_group 1;" ::: "memory");
        } else {
            asm volatile("cp.async.wait_group 0;" ::: "memory");
        }
        __syncthreads();

        const int s = t & 1;
        const uint32_t* Au = (const uint32_t*)(smem + s * 2 * TILE_B);
        const uint32_t* Bu = (const uint32_t*)(smem + s * 2 * TILE_B + TILE_B);

        const int g = lid >> 2;
        const int lg = lid & 3;

#pragma unroll
        for (int kk = 0; kk < 4; kk++) {
            const int kU = kk * 8;      // u32 offset of this k16 block
            uint32_t a[2][4];
#pragma unroll
            for (int mt = 0; mt < 2; mt++) {
                const int r0 = wm * 32 + mt * 16 + g;
                a[mt][0] = Au[(r0)     * 36 + kU + lg];
                a[mt][1] = Au[(r0 + 8) * 36 + kU + lg];
                a[mt][2] = Au[(r0)     * 36 + kU + lg + 4];
                a[mt][3] = Au[(r0 + 8) * 36 + kU + lg + 4];
            }
#pragma unroll
            for (int nt = 0; nt < 8; nt++) {
                const int c0 = wn * 64 + nt * 8 + g;
                uint32_t b[2];
                b[0] = Bu[c0 * 36 + kU + lg];
                b[1] = Bu[c0 * 36 + kU + lg + 4];
                mma_f16(acc[0][nt], a[0], b);
                mma_f16(acc[1][nt], a[1], b);
            }
        }
        __syncthreads();
    }

    // ---- epilogue: bias + ELU; fp32 or fp16 stores ----
    const int g = lid >> 2;
    const int lg = lid & 3;
    float* Cf = (float*)Cv;
    __half* Ch = (__half*)Cv;
#pragma unroll
    for (int mt = 0; mt < 2; mt++) {
        const int r0 = m0 + wm * 32 + mt * 16 + g;
#pragma unroll
        for (int nt = 0; nt < 8; nt++) {
            const int col = n0 + wn * 64 + nt * 8 + lg * 2;
            float b0 = 0.f, b1 = 0.f;
            if (bias) { b0 = __ldg(&bias[col]); b1 = __ldg(&bias[col + 1]); }
            float x0 = acc[mt][nt][0] + b0;
            float x1 = acc[mt][nt][1] + b1;
            float x2 = acc[mt][nt][2] + b0;
            float x3 = acc[mt][nt][3] + b1;
            if (do_elu) {
                x0 = (x0 > 0.f) ? x0 : expm1f(x0);
                x1 = (x1 > 0.f) ? x1 : expm1f(x1);
                x2 = (x2 > 0.f) ? x2 : expm1f(x2);
                x3 = (x3 > 0.f) ? x3 : expm1f(x3);
            }
            if (out_half) {
                if (r0 < M)
                    *(__half2*)(Ch + (size_t)r0 * ldc + col) =
                        __floats2half2_rn(x0, x1);
                if (r0 + 8 < M)
                    *(__half2*)(Ch + (size_t)(r0 + 8) * ldc + col) =
                        __floats2half2_rn(x2, x3);
            } else {
                if (r0 < M)
                    *(float2*)(Cf + (size_t)r0 * ldc + col) = make_float2(x0, x1);
                if (r0 + 8 < M)
                    *(float2*)(Cf + (size_t)(r0 + 8) * ldc + col) =
                        make_float2(x2, x3);
            }
        }
    }
}

// ---------------------------------------------------------------------------
// Aggregation over fp16 xw: 8 nodes / 256-thread block, 32 threads per node,
// uint4 (8 halves) per lane, fp32 accumulation, x2-unrolled gather.
__device__ __forceinline__ void h8_fma(float2* acc, uint4 v, float w) {
    const __half2* h = (const __half2*)&v;
#pragma unroll
    for (int j = 0; j < 4; j++) {
        float2 f = __half22float2(h[j]);
        acc[j].x += f.x * w;
        acc[j].y += f.y * w;
    }
}

__global__ __launch_bounds__(256) void agg_kernel(const float* __restrict__ bg,
                                                  int N) {
    const int row = blockIdx.x * 8 + (threadIdx.x >> 5);
    const int t = threadIdx.x & 31;
    if (row >= N) return;
    const uint4* xw4 = (const uint4*)g_xw_h;
    const int cnt = g_count[row];
    const float inv_deg = 1.0f / (float)(cnt + 1);
    const float dinv_r = g_dinv[row];

    float2 acc[4] = {{0.f,0.f},{0.f,0.f},{0.f,0.f},{0.f,0.f}};
    h8_fma(acc, xw4[(size_t)row * 32 + t], inv_deg);

    const int beg = g_offsets[row], end = beg + cnt;
    int e = beg;
    for (; e + 2 <= end; e += 2) {
        int s0 = g_csr[e], s1 = g_csr[e + 1];
        float w0 = dinv_r * __ldg(&g_dinv[s0]);
        float w1 = dinv_r * __ldg(&g_dinv[s1]);
        uint4 x0 = __ldg(&xw4[(size_t)s0 * 32 + t]);
        uint4 x1 = __ldg(&xw4[(size_t)s1 * 32 + t]);
        h8_fma(acc, x0, w0);
        h8_fma(acc, x1, w1);
    }
    if (e < end) {
        int s0 = g_csr[e];
        float w0 = dinv_r * __ldg(&g_dinv[s0]);
        h8_fma(acc, __ldg(&xw4[(size_t)s0 * 32 + t]), w0);
    }

    const float4* bg4 = (const float4*)bg;
    float4 b0 = __ldg(&bg4[t * 2]);
    float4 b1 = __ldg(&bg4[t * 2 + 1]);
    acc[0].x += b0.x; acc[0].y += b0.y;
    acc[1].x += b0.z; acc[1].y += b0.w;
    acc[2].x += b1.x; acc[2].y += b1.y;
    acc[3].x += b1.z; acc[3].y += b1.w;

    uint4 o;
    __half2* oh = (__half2*)&o;
#pragma unroll
    for (int j = 0; j < 4; j++)
        oh[j] = __floats2half2_rn(acc[j].x, acc[j].y);
    ((uint4*)g_gc_h)[(size_t)row * 32 + t] = o;
}

// ---------------------------------------------------------------------------
__global__ void copy_feats_kernel(const float4* __restrict__ feats4,
                                  float4* __restrict__ out4, int N) {
    int tot = N * 32;
    for (int i = blockIdx.x * blockDim.x + threadIdx.x; i < tot;
         i += gridDim.x * blockDim.x) {
        int r = i >> 5, c = i & 31;
        out4[(size_t)r * 96 + 64 + c] = feats4[i];
    }
}

__global__ void copy_tail_kernel(const void* __restrict__ edges,
                                 const void* __restrict__ batch,
                                 float* __restrict__ out, int N, int E,
                                 long long tailMax) {
    size_t base = (size_t)N * (FO + INF);
    long long tot = 2LL * E + N;
    if (tot > tailMax) tot = tailMax;
    for (long long i = blockIdx.x * (long long)blockDim.x + threadIdx.x; i < tot;
         i += (long long)gridDim.x * blockDim.x) {
        long long v = (i < 2LL * E) ? ld_idx(edges, i) : ld_idx(batch, i - 2LL * E);
        out[base + i] = (float)v;
    }
}

// ---------------------------------------------------------------------------
extern "C" void kernel_launch(void* const* d_in, const int* in_sizes, int n_in,
                              void* d_out, int out_size) {
    const float* feats = (const float*)d_in[0];
    const void*  edges = d_in[1];
    const void*  batch = d_in[2];
    const float* W1    = (const float*)d_in[3];
    const float* b1    = (const float*)d_in[4];
    const float* Wg    = (const float*)d_in[5];
    const float* bg    = (const float*)d_in[6];
    const float* Wc    = (const float*)d_in[7];
    const float* bc    = (const float*)d_in[8];
    float* out = (float*)d_out;

    const int N = NN, E = EE;
    const int nBlk = (N + 255) / 256;  // 391

    __half *p_fh, *p_nfh, *p_gch, *p_xwh, *p_w1t, *p_wgt, *p_wct;
    cudaGetSymbolAddress((void**)&p_fh, g_feats_h);
    cudaGetSymbolAddress((void**)&p_nfh, g_nfeats_h);
    cudaGetSymbolAddress((void**)&p_gch, g_gc_h);
    cudaGetSymbolAddress((void**)&p_xwh, g_xw_h);
    cudaGetSymbolAddress((void**)&p_w1t, g_W1T);
    cudaGetSymbolAddress((void**)&p_wgt, g_WgT);
    cudaGetSymbolAddress((void**)&p_wct, g_WcT);

    static cudaStream_t s1 = nullptr;
    static cudaEvent_t evFork = nullptr, evCSR = nullptr, evSide = nullptr,
                       evWT = nullptr;
    if (!s1) {
        cudaFuncSetAttribute(tc_gemm, cudaFuncAttributeMaxDynamicSharedMemorySize,
                             GEMM_SMEM);
        cudaStreamCreateWithFlags(&s1, cudaStreamNonBlocking);
        cudaEventCreateWithFlags(&evFork, cudaEventDisableTiming);
        cudaEventCreateWithFlags(&evCSR, cudaEventDisableTiming);
        cudaEventCreateWithFlags(&evSide, cudaEventDisableTiming);
        cudaEventCreateWithFlags(&evWT, cudaEventDisableTiming);
    }

    // ---- fork side stream ----
    cudaEventRecord(evFork, 0);
    cudaStreamWaitEvent(s1, evFork, 0);

    const int nMT = (N + BM - 1) / BM;  // 782
    dim3 grid(2, nMT);

    // main: feats fp32 -> fp16
    convert_feats_kernel<<<256, 256>>>((const float4*)feats, N * INF / 4);
    // side: all weight transposes (fp16) -- overlaps convert
    transpose_all_kernel<<<256, 256, 0, s1>>>(W1, Wg, Wc);
    cudaEventRecord(evWT, s1);
    // side: CSR prologue
    detect_kernel<<<1, 256, 0, s1>>>((const unsigned int*)edges, 4096);
    zero_kernel<<<256, 256, 0, s1>>>(N);
    hist_kernel<<<512, 256, 0, s1>>>(edges, E);

    // main: GEMM1 -- needs W1T + feats_h
    cudaStreamWaitEvent(0, evWT, 0);
    tc_gemm<<<grid, 256, GEMM_SMEM>>>(p_fh, INF, nullptr, 0, p_w1t, b1,
                                      p_nfh, HID, N, 1, 1);

    // side: rest of CSR chain + output copies
    scan1_kernel<<<nBlk, 256, 0, s1>>>(N);
    scan2_kernel<<<1, 512, 0, s1>>>(nBlk, N);
    scan3_kernel<<<nBlk, 256, 0, s1>>>(N);
    dinv_kernel<<<256, 256, 0, s1>>>(N);
    scatter_kernel<<<512, 256, 0, s1>>>(edges, E);
    cudaEventRecord(evCSR, s1);
    copy_feats_kernel<<<512, 256, 0, s1>>>((const float4*)feats, (float4*)out, N);
    long long tailMax = (long long)out_size - (long long)N * (FO + INF);
    if (tailMax > 0)
        copy_tail_kernel<<<512, 256, 0, s1>>>(edges, batch, out, N, E, tailMax);
    cudaEventRecord(evSide, s1);

    // main: GEMM2 -> xw fp16 (no bias)
    tc_gemm<<<grid, 256, GEMM_SMEM>>>(p_nfh, HID, p_fh, INF, p_wgt, nullptr,
                                      p_xwh, GCO, N, 0, 1);

    // join: aggregation needs CSR + xw; writes gc fp16
    cudaStreamWaitEvent(0, evCSR, 0);
    agg_kernel<<<(N + 7) / 8, 256>>>(bg, N);

    // main: GEMM3 -> out[:, :256] fp32, row stride 384
    tc_gemm<<<grid, 256, GEMM_SMEM>>>(p_nfh, HID, p_gch, GCO, p_wct, bc,
                                      out, FO + INF, N, 1, 0);

    // join side-stream copies before returning
    cudaStreamWaitEvent(0, evSide, 0);
}

// round 15
// speedup vs baseline: 1.1843x; 1.1843x over previous
#include <cuda_runtime.h>
#include <cuda_fp16.h>
#include <math.h>
#include <stdint.h>

#define NN 100000
#define EE 1600000
#define INF 128
#define HID 256
#define GCO 256
#define FO  256

// ---- fp16 mma.sync GEMM tile config (R13 proven optimum) --------------------
#define BM 128
#define BN 128
#define BK 32                        // K elements per tile
#define LDH 72                       // smem row stride in halves (144B)
#define TILE_B (128 * LDH * 2)       // 18432 bytes (A or B tile)
#define NSTAGE 2
#define GEMM_SMEM (NSTAGE * 2 * TILE_B)   // 73728 bytes -> 3 CTAs/SM

__device__ __forceinline__ uint32_t smem_u32(const void* p) {
    uint32_t a;
    asm("{ .reg .u64 t; cvta.to.shared.u64 t, %1; cvt.u32.u64 %0, t; }"
        : "=r"(a) : "l"(p));
    return a;
}

__device__ __forceinline__ void cp16(uint32_t dst, const void* src, int sz) {
    asm volatile("cp.async.cg.shared.global [%0], [%1], 16, %2;"
                 :: "r"(dst), "l"(src), "r"(sz) : "memory");
}

__device__ __forceinline__ void mma_f16(float* d, const uint32_t* a,
                                        const uint32_t* b) {
    asm volatile(
        "mma.sync.aligned.m16n8k16.row.col.f32.f16.f16.f32 "
        "{%0,%1,%2,%3}, {%4,%5,%6,%7}, {%8,%9}, {%0,%1,%2,%3};"
        : "+f"(d[0]), "+f"(d[1]), "+f"(d[2]), "+f"(d[3])
        : "r"(a[0]), "r"(a[1]), "r"(a[2]), "r"(a[3]), "r"(b[0]), "r"(b[1]));
}

// ---------------------------------------------------------------------------
// Scratch (device globals: allocation-free)
__device__ __align__(16) __half g_feats_h[(size_t)NN * INF];
__device__ __align__(16) __half g_nfeats_h[(size_t)NN * HID];
__device__ __align__(16) __half g_xw_h[(size_t)NN * GCO];
__device__ __align__(16) __half g_gc_h[(size_t)NN * GCO];
__device__ __align__(16) __half g_W1T[HID * INF];
__device__ __align__(16) __half g_WgT[GCO * (HID + INF)];
__device__ __align__(16) __half g_WcT[FO * (HID + GCO)];
__device__ int   g_count[NN];
__device__ int   g_cursor[NN];
__device__ int   g_offsets[NN + 1];
__device__ float g_dinv[NN];
__device__ int   g_csr[EE];
__device__ int   g_bsum[512];
__device__ int   g_boff[512];
__device__ int   g_is64;

// ---------------------------------------------------------------------------
__global__ void detect_kernel(const unsigned int* __restrict__ ew, int nPairs) {
    __shared__ int nz;
    if (threadIdx.x == 0) nz = 0;
    __syncthreads();
    for (int i = threadIdx.x; i < nPairs; i += blockDim.x)
        if (ew[2 * i + 1] != 0u) { nz = 1; break; }
    __syncthreads();
    if (threadIdx.x == 0) g_is64 = (nz == 0) ? 1 : 0;
}

__device__ __forceinline__ long long ld_idx(const void* p, size_t i) {
    if (g_is64) return ((const long long*)p)[i];
    return (long long)((const int*)p)[i];
}

__global__ void zero_kernel(int n) {
    for (int i = blockIdx.x * blockDim.x + threadIdx.x; i < n;
         i += gridDim.x * blockDim.x) {
        g_count[i] = 0;
        g_cursor[i] = 0;
    }
}

__global__ void hist_kernel(const void* __restrict__ edges, int E) {
    for (int i = blockIdx.x * blockDim.x + threadIdx.x; i < E;
         i += gridDim.x * blockDim.x) {
        int d = (int)ld_idx(edges, (size_t)E + i);
        if (d >= 0 && d < NN) atomicAdd(&g_count[d], 1);
    }
}

__global__ void scan1_kernel(int n) {
    __shared__ int sh[256];
    int i = blockIdx.x * 256 + threadIdx.x;
    sh[threadIdx.x] = (i < n) ? g_count[i] : 0;
    __syncthreads();
    for (int off = 128; off > 0; off >>= 1) {
        if (threadIdx.x < off) sh[threadIdx.x] += sh[threadIdx.x + off];
        __syncthreads();
    }
    if (threadIdx.x == 0) g_bsum[blockIdx.x] = sh[0];
}

__global__ void scan2_kernel(int nb, int n) {
    __shared__ int sh[512];
    int t = threadIdx.x;
    int v = (t < nb) ? g_bsum[t] : 0;
    sh[t] = v;
    __syncthreads();
    for (int off = 1; off < 512; off <<= 1) {
        int x = (t >= off) ? sh[t - off] : 0;
        __syncthreads();
        sh[t] += x;
        __syncthreads();
    }
    if (t < nb) g_boff[t] = sh[t] - v;
    if (t == nb - 1) g_offsets[n] = sh[t];
}

__global__ void scan3_kernel(int n) {
    __shared__ int sh[256];
    int b = blockIdx.x, t = threadIdx.x;
    int i = b * 256 + t;
    int v = (i < n) ? g_count[i] : 0;
    sh[t] = v;
    __syncthreads();
    for (int off = 1; off < 256; off <<= 1) {
        int x = (t >= off) ? sh[t - off] : 0;
        __syncthreads();
        sh[t] += x;
        __syncthreads();
    }
    if (i < n) g_offsets[i] = sh[t] - v + g_boff[b];
}

__global__ void dinv_kernel(int n) {
    for (int i = blockIdx.x * blockDim.x + threadIdx.x; i < n;
         i += gridDim.x * blockDim.x)
        g_dinv[i] = rsqrtf((float)(g_count[i] + 1));
}

__global__ void scatter_kernel(const void* __restrict__ edges, int E) {
    for (int i = blockIdx.x * blockDim.x + threadIdx.x; i < E;
         i += gridDim.x * blockDim.x) {
        int s = (int)ld_idx(edges, i);
        int d = (int)ld_idx(edges, (size_t)E + i);
        if (s < 0 || s >= NN || d < 0 || d >= NN) continue;
        int pos = g_offsets[d] + atomicAdd(&g_cursor[d], 1);
        g_csr[pos] = s;
    }
}

// ---------------------------------------------------------------------------
// feats fp32 -> fp16 (rn)
__global__ void convert_feats_kernel(const float4* __restrict__ f4, int n4) {
    __half2* o2 = (__half2*)g_feats_h;
    for (int i = blockIdx.x * blockDim.x + threadIdx.x; i < n4;
         i += gridDim.x * blockDim.x) {
        float4 v = f4[i];
        o2[2 * i]     = __floats2half2_rn(v.x, v.y);
        o2[2 * i + 1] = __floats2half2_rn(v.z, v.w);
    }
}

// All 3 weight transposes fused: W[K,256] -> WT[256,K], fp16 (rn).
__global__ void transpose_all_kernel(const float* __restrict__ W1,
                                     const float* __restrict__ Wg,
                                     const float* __restrict__ Wc) {
    const int T1 = INF * 256;
    const int T2 = (HID + INF) * 256;
    const int T3 = (HID + GCO) * 256;
    int tot = T1 + T2 + T3;
    for (int i = blockIdx.x * blockDim.x + threadIdx.x; i < tot;
         i += gridDim.x * blockDim.x) {
        const float* W; __half* WT; int K, j;
        if (i < T1)           { W = W1; WT = g_W1T; K = INF;       j = i; }
        else if (i < T1 + T2) { W = Wg; WT = g_WgT; K = HID + INF; j = i - T1; }
        else                  { W = Wc; WT = g_WcT; K = HID + GCO; j = i - T1 - T2; }
        int k = j >> 8, n = j & 255;
        WT[(size_t)n * K + k] = __float2half_rn(W[(size_t)k * 256 + n]);
    }
}

// ---------------------------------------------------------------------------
// fp16 mma.sync GEMM: C[M,256] = concat_k(A1[M,K1], A2[M,K2]) @ WT^T
// 2-stage cp.async pipeline, 3 CTAs/SM (launch_bounds 256,3).
__global__ __launch_bounds__(256, 3) void tc_gemm(
    const __half* __restrict__ A1, int K1,
    const __half* __restrict__ A2, int K2,
    const __half* __restrict__ BT,
    const float* __restrict__ bias,
    void* __restrict__ Cv, int ldc, int M, int do_elu, int out_half)
{
    extern __shared__ char smem[];
    const uint32_t sb = smem_u32(smem);
    const int tid = threadIdx.x;
    const int wid = tid >> 5, lid = tid & 31;
    const int wm = wid >> 1, wn = wid & 1;
    const int m0 = blockIdx.y * BM;
    const int n0 = blockIdx.x * BN;
    const int Ktot = K1 + K2;
    const int nT = Ktot / BK;

    const int ldr = tid >> 1;           // 0..127 (tile row)
    const int ldh = (tid & 1) * 16;     // 0 or 16 halves (32B)

    float acc[2][8][4];
#pragma unroll
    for (int i = 0; i < 2; i++)
#pragma unroll
        for (int j = 0; j < 8; j++)
#pragma unroll
            for (int q = 0; q < 4; q++) acc[i][j][q] = 0.f;

    auto load_stage = [&](int t) {
        const int s = t & 1;
        const uint32_t aOff = s * 2 * TILE_B;
        const uint32_t bOff = aOff + TILE_B;
        const int k0 = t * BK;
        const __half* A; int K, kc;
        if (k0 < K1) { A = A1; K = K1; kc = k0; }
        else         { A = A2; K = K2; kc = k0 - K1; }
        const int arow = m0 + ldr;
        const int asz = (arow < M) ? 16 : 0;
        const __half* asrc = A + (size_t)arow * K + kc + ldh;
        const __half* bsrc = BT + (size_t)(n0 + ldr) * Ktot + k0 + ldh;
        const uint32_t adst = sb + aOff + (ldr * LDH + ldh) * 2;
        const uint32_t bdst = sb + bOff + (ldr * LDH + ldh) * 2;
#pragma unroll
        for (int j = 0; j < 2; j++) {
            cp16(adst + j * 16, asrc + j * 8, asz);
            cp16(bdst + j * 16, bsrc + j * 8, 16);
        }
        asm volatile("cp.async.commit_group;" ::: "memory");
    };

    load_stage(0);

    for (int t = 0; t < nT; t++) {
        if (t + 1 < nT) {
            load_stage(t + 1);
            asm volatile("cp.async.wait_group 1;" ::: "memory");
        } else {
            asm volatile("cp.async.wait_group 0;" ::: "memory");
        }
        __syncthreads();

        const int s = t & 1;
        const uint32_t* Au = (const uint32_t*)(smem + s * 2 * TILE_B);
        const uint32_t* Bu = (const uint32_t*)(smem + s * 2 * TILE_B + TILE_B);

        const int g = lid >> 2;
        const int lg = lid & 3;

#pragma unroll
        for (int kk = 0; kk < 2; kk++) {
            const int kU = kk * 8;
            uint32_t a[2][4];
#pragma unroll
            for (int mt = 0; mt < 2; mt++) {
                const int r0 = wm * 32 + mt * 16 + g;
                a[mt][0] = Au[(r0)     * 36 + kU + lg];
                a[mt][1] = Au[(r0 + 8) * 36 + kU + lg];
                a[mt][2] = Au[(r0)     * 36 + kU + lg + 4];
                a[mt][3] = Au[(r0 + 8) * 36 + kU + lg + 4];
            }
#pragma unroll
            for (int nt = 0; nt < 8; nt++) {
                const int c0 = wn * 64 + nt * 8 + g;
                uint32_t b[2];
                b[0] = Bu[c0 * 36 + kU + lg];
                b[1] = Bu[c0 * 36 + kU + lg + 4];
                mma_f16(acc[0][nt], a[0], b);
                mma_f16(acc[1][nt], a[1], b);
            }
        }
        __syncthreads();
    }

    // ---- epilogue: bias + ELU; fp32 or fp16 stores ----
    const int g = lid >> 2;
    const int lg = lid & 3;
    float* Cf = (float*)Cv;
    __half* Ch = (__half*)Cv;
#pragma unroll
    for (int mt = 0; mt < 2; mt++) {
        const int r0 = m0 + wm * 32 + mt * 16 + g;
#pragma unroll
        for (int nt = 0; nt < 8; nt++) {
            const int col = n0 + wn * 64 + nt * 8 + lg * 2;
            float b0 = 0.f, b1 = 0.f;
            if (bias) { b0 = __ldg(&bias[col]); b1 = __ldg(&bias[col + 1]); }
            float x0 = acc[mt][nt][0] + b0;
            float x1 = acc[mt][nt][1] + b1;
            float x2 = acc[mt][nt][2] + b0;
            float x3 = acc[mt][nt][3] + b1;
            if (do_elu) {
                x0 = (x0 > 0.f) ? x0 : expm1f(x0);
                x1 = (x1 > 0.f) ? x1 : expm1f(x1);
                x2 = (x2 > 0.f) ? x2 : expm1f(x2);
                x3 = (x3 > 0.f) ? x3 : expm1f(x3);
            }
            if (out_half) {
                if (r0 < M)
                    *(__half2*)(Ch + (size_t)r0 * ldc + col) =
                        __floats2half2_rn(x0, x1);
                if (r0 + 8 < M)
                    *(__half2*)(Ch + (size_t)(r0 + 8) * ldc + col) =
                        __floats2half2_rn(x2, x3);
            } else {
                if (r0 < M)
                    *(float2*)(Cf + (size_t)r0 * ldc + col) = make_float2(x0, x1);
                if (r0 + 8 < M)
                    *(float2*)(Cf + (size_t)(r0 + 8) * ldc + col) =
                        make_float2(x2, x3);
            }
        }
    }
}

// ---------------------------------------------------------------------------
// Aggregation over fp16 xw: 8 nodes / 256-thread block, 32 threads per node,
// uint4 (8 halves) per lane, fp32 accumulation, x2-unrolled gather.
__device__ __forceinline__ void h8_fma(float2* acc, uint4 v, float w) {
    const __half2* h = (const __half2*)&v;
#pragma unroll
    for (int j = 0; j < 4; j++) {
        float2 f = __half22float2(h[j]);
        acc[j].x += f.x * w;
        acc[j].y += f.y * w;
    }
}

__global__ __launch_bounds__(256) void agg_kernel(const float* __restrict__ bg,
                                                  int N) {
    const int row = blockIdx.x * 8 + (threadIdx.x >> 5);
    const int t = threadIdx.x & 31;
    if (row >= N) return;
    const uint4* xw4 = (const uint4*)g_xw_h;
    const int cnt = g_count[row];
    const float inv_deg = 1.0f / (float)(cnt + 1);
    const float dinv_r = g_dinv[row];

    float2 acc[4] = {{0.f,0.f},{0.f,0.f},{0.f,0.f},{0.f,0.f}};
    h8_fma(acc, xw4[(size_t)row * 32 + t], inv_deg);

    const int beg = g_offsets[row], end = beg + cnt;
    int e = beg;
    for (; e + 2 <= end; e += 2) {
        int s0 = g_csr[e], s1 = g_csr[e + 1];
        float w0 = dinv_r * __ldg(&g_dinv[s0]);
        float w1 = dinv_r * __ldg(&g_dinv[s1]);
        uint4 x0 = __ldg(&xw4[(size_t)s0 * 32 + t]);
        uint4 x1 = __ldg(&xw4[(size_t)s1 * 32 + t]);
        h8_fma(acc, x0, w0);
        h8_fma(acc, x1, w1);
    }
    if (e < end) {
        int s0 = g_csr[e];
        float w0 = dinv_r * __ldg(&g_dinv[s0]);
        h8_fma(acc, __ldg(&xw4[(size_t)s0 * 32 + t]), w0);
    }

    const float4* bg4 = (const float4*)bg;
    float4 b0 = __ldg(&bg4[t * 2]);
    float4 b1 = __ldg(&bg4[t * 2 + 1]);
    acc[0].x += b0.x; acc[0].y += b0.y;
    acc[1].x += b0.z; acc[1].y += b0.w;
    acc[2].x += b1.x; acc[2].y += b1.y;
    acc[3].x += b1.z; acc[3].y += b1.w;

    uint4 o;
    __half2* oh = (__half2*)&o;
#pragma unroll
    for (int j = 0; j < 4; j++)
        oh[j] = __floats2half2_rn(acc[j].x, acc[j].y);
    ((uint4*)g_gc_h)[(size_t)row * 32 + t] = o;
}

// ---------------------------------------------------------------------------
__global__ void copy_feats_kernel(const float4* __restrict__ feats4,
                                  float4* __restrict__ out4, int N) {
    int tot = N * 32;
    for (int i = blockIdx.x * blockDim.x + threadIdx.x; i < tot;
         i += gridDim.x * blockDim.x) {
        int r = i >> 5, c = i & 31;
        out4[(size_t)r * 96 + 64 + c] = feats4[i];
    }
}

__global__ void copy_tail_kernel(const void* __restrict__ edges,
                                 const void* __restrict__ batch,
                                 float* __restrict__ out, int N, int E,
                                 long long tailMax) {
    size_t base = (size_t)N * (FO + INF);
    long long tot = 2LL * E + N;
    if (tot > tailMax) tot = tailMax;
    for (long long i = blockIdx.x * (long long)blockDim.x + threadIdx.x; i < tot;
         i += (long long)gridDim.x * blockDim.x) {
        long long v = (i < 2LL * E) ? ld_idx(edges, i) : ld_idx(batch, i - 2LL * E);
        out[base + i] = (float)v;
    }
}

// ---------------------------------------------------------------------------
extern "C" void kernel_launch(void* const* d_in, const int* in_sizes, int n_in,
                              void* d_out, int out_size) {
    const float* feats = (const float*)d_in[0];
    const void*  edges = d_in[1];
    const void*  batch = d_in[2];
    const float* W1    = (const float*)d_in[3];
    const float* b1    = (const float*)d_in[4];
    const float* Wg    = (const float*)d_in[5];
    const float* bg    = (const float*)d_in[6];
    const float* Wc    = (const float*)d_in[7];
    const float* bc    = (const float*)d_in[8];
    float* out = (float*)d_out;

    const int N = NN, E = EE;
    const int nBlk = (N + 255) / 256;  // 391

    __half *p_fh, *p_nfh, *p_gch, *p_xwh, *p_w1t, *p_wgt, *p_wct;
    cudaGetSymbolAddress((void**)&p_fh, g_feats_h);
    cudaGetSymbolAddress((void**)&p_nfh, g_nfeats_h);
    cudaGetSymbolAddress((void**)&p_gch, g_gc_h);
    cudaGetSymbolAddress((void**)&p_xwh, g_xw_h);
    cudaGetSymbolAddress((void**)&p_w1t, g_W1T);
    cudaGetSymbolAddress((void**)&p_wgt, g_WgT);
    cudaGetSymbolAddress((void**)&p_wct, g_WcT);

    static cudaStream_t s1 = nullptr;
    static cudaEvent_t evFork = nullptr, evCSR = nullptr, evSide = nullptr,
                       evWT = nullptr;
    if (!s1) {
        cudaFuncSetAttribute(tc_gemm, cudaFuncAttributeMaxDynamicSharedMemorySize,
                             GEMM_SMEM);
        cudaStreamCreateWithFlags(&s1, cudaStreamNonBlocking);
        cudaEventCreateWithFlags(&evFork, cudaEventDisableTiming);
        cudaEventCreateWithFlags(&evCSR, cudaEventDisableTiming);
        cudaEventCreateWithFlags(&evSide, cudaEventDisableTiming);
        cudaEventCreateWithFlags(&evWT, cudaEventDisableTiming);
    }

    // ---- fork side stream ----
    cudaEventRecord(evFork, 0);
    cudaStreamWaitEvent(s1, evFork, 0);

    const int nMT = (N + BM - 1) / BM;  // 782
    dim3 grid(2, nMT);

    // main: feats fp32 -> fp16
    convert_feats_kernel<<<256, 256>>>((const float4*)feats, N * INF / 4);
    // side: all weight transposes (fp16) -- overlaps convert
    transpose_all_kernel<<<256, 256, 0, s1>>>(W1, Wg, Wc);
    cudaEventRecord(evWT, s1);
    // side: CSR prologue
    detect_kernel<<<1, 256, 0, s1>>>((const unsigned int*)edges, 4096);
    zero_kernel<<<256, 256, 0, s1>>>(N);
    hist_kernel<<<512, 256, 0, s1>>>(edges, E);

    // main: GEMM1 -- needs W1T + feats_h
    cudaStreamWaitEvent(0, evWT, 0);
    tc_gemm<<<grid, 256, GEMM_SMEM>>>(p_fh, INF, nullptr, 0, p_w1t, b1,
                                      p_nfh, HID, N, 1, 1);

    // side: rest of CSR chain + output copies
    scan1_kernel<<<nBlk, 256, 0, s1>>>(N);
    scan2_kernel<<<1, 512, 0, s1>>>(nBlk, N);
    scan3_kernel<<<nBlk, 256, 0, s1>>>(N);
    dinv_kernel<<<256, 256, 0, s1>>>(N);
    scatter_kernel<<<512, 256, 0, s1>>>(edges, E);
    cudaEventRecord(evCSR, s1);
    copy_feats_kernel<<<512, 256, 0, s1>>>((const float4*)feats, (float4*)out, N);
    long long tailMax = (long long)out_size - (long long)N * (FO + INF);
    if (tailMax > 0)
        copy_tail_kernel<<<512, 256, 0, s1>>>(edges, batch, out, N, E, tailMax);
    cudaEventRecord(evSide, s1);

    // main: GEMM2 -> xw fp16 (no bias)
    tc_gemm<<<grid, 256, GEMM_SMEM>>>(p_nfh, HID, p_fh, INF, p_wgt, nullptr,
                                      p_xwh, GCO, N, 0, 1);

    // join: aggregation needs CSR + xw; writes gc fp16
    cudaStreamWaitEvent(0, evCSR, 0);
    agg_kernel<<<(N + 7) / 8, 256>>>(bg, N);

    // main: GEMM3 -> out[:, :256] fp32, row stride 384
    tc_gemm<<<grid, 256, GEMM_SMEM>>>(p_nfh, HID, p_gch, GCO, p_wct, bc,
                                      out, FO + INF, N, 1, 0);

    // join side-stream copies before returning
    cudaStreamWaitEvent(0, evSide, 0);
}

// round 16
// speedup vs baseline: 1.2555x; 1.0602x over previous
#include <cuda_runtime.h>
#include <cuda_fp16.h>
#include <math.h>
#include <stdint.h>

#define NN 100000
#define EE 1600000
#define INF 128
#define HID 256
#define GCO 256
#define FO  256

// ---- fp16 mma.sync GEMM tile config (R13 proven optimum) --------------------
#define BM 128
#define BN 128
#define BK 32                        // K elements per tile
#define LDH 72                       // smem row stride in halves (144B)
#define TILE_B (128 * LDH * 2)       // 18432 bytes (A or B tile)
#define NSTAGE 2
#define GEMM_SMEM (NSTAGE * 2 * TILE_B)   // 73728 bytes -> 3 CTAs/SM

__device__ __forceinline__ uint32_t smem_u32(const void* p) {
    uint32_t a;
    asm("{ .reg .u64 t; cvta.to.shared.u64 t, %1; cvt.u32.u64 %0, t; }"
        : "=r"(a) : "l"(p));
    return a;
}

__device__ __forceinline__ void cp16(uint32_t dst, const void* src, int sz) {
    asm volatile("cp.async.cg.shared.global [%0], [%1], 16, %2;"
                 :: "r"(dst), "l"(src), "r"(sz) : "memory");
}

__device__ __forceinline__ void mma_f16(float* d, const uint32_t* a,
                                        const uint32_t* b) {
    asm volatile(
        "mma.sync.aligned.m16n8k16.row.col.f32.f16.f16.f32 "
        "{%0,%1,%2,%3}, {%4,%5,%6,%7}, {%8,%9}, {%0,%1,%2,%3};"
        : "+f"(d[0]), "+f"(d[1]), "+f"(d[2]), "+f"(d[3])
        : "r"(a[0]), "r"(a[1]), "r"(a[2]), "r"(a[3]), "r"(b[0]), "r"(b[1]));
}

// Fast ELU: MUFU-based exp (rel err ~1e-7, negligible vs fp16 path)
__device__ __forceinline__ float elu_fast(float x) {
    return (x > 0.f) ? x : (__expf(x) - 1.0f);
}

// ---------------------------------------------------------------------------
// Scratch (device globals: allocation-free)
__device__ __align__(16) __half g_feats_h[(size_t)NN * INF];
__device__ __align__(16) __half g_nfeats_h[(size_t)NN * HID];
__device__ __align__(16) __half g_xw_h[(size_t)NN * GCO];
__device__ __align__(16) __half g_gc_h[(size_t)NN * GCO];
__device__ __align__(16) __half g_W1T[HID * INF];
__device__ __align__(16) __half g_WgT[GCO * (HID + INF)];
__device__ __align__(16) __half g_WcT[FO * (HID + GCO)];
__device__ int   g_count[NN];
__device__ int   g_cursor[NN];
__device__ int   g_offsets[NN + 1];
__device__ float g_dinv[NN];
__device__ int   g_csr[EE];
__device__ int   g_bsum[512];
__device__ int   g_boff[512];
__device__ int   g_is64;

// ---------------------------------------------------------------------------
__global__ void detect_kernel(const unsigned int* __restrict__ ew, int nPairs) {
    __shared__ int nz;
    if (threadIdx.x == 0) nz = 0;
    __syncthreads();
    for (int i = threadIdx.x; i < nPairs; i += blockDim.x)
        if (ew[2 * i + 1] != 0u) { nz = 1; break; }
    __syncthreads();
    if (threadIdx.x == 0) g_is64 = (nz == 0) ? 1 : 0;
}

__device__ __forceinline__ long long ld_idx(const void* p, size_t i) {
    if (g_is64) return ((const long long*)p)[i];
    return (long long)((const int*)p)[i];
}

__global__ void zero_kernel(int n) {
    for (int i = blockIdx.x * blockDim.x + threadIdx.x; i < n;
         i += gridDim.x * blockDim.x) {
        g_count[i] = 0;
        g_cursor[i] = 0;
    }
}

__global__ void hist_kernel(const void* __restrict__ edges, int E) {
    for (int i = blockIdx.x * blockDim.x + threadIdx.x; i < E;
         i += gridDim.x * blockDim.x) {
        int d = (int)ld_idx(edges, (size_t)E + i);
        if (d >= 0 && d < NN) atomicAdd(&g_count[d], 1);
    }
}

__global__ void scan1_kernel(int n) {
    __shared__ int sh[256];
    int i = blockIdx.x * 256 + threadIdx.x;
    sh[threadIdx.x] = (i < n) ? g_count[i] : 0;
    __syncthreads();
    for (int off = 128; off > 0; off >>= 1) {
        if (threadIdx.x < off) sh[threadIdx.x] += sh[threadIdx.x + off];
        __syncthreads();
    }
    if (threadIdx.x == 0) g_bsum[blockIdx.x] = sh[0];
}

__global__ void scan2_kernel(int nb, int n) {
    __shared__ int sh[512];
    int t = threadIdx.x;
    int v = (t < nb) ? g_bsum[t] : 0;
    sh[t] = v;
    __syncthreads();
    for (int off = 1; off < 512; off <<= 1) {
        int x = (t >= off) ? sh[t - off] : 0;
        __syncthreads();
        sh[t] += x;
        __syncthreads();
    }
    if (t < nb) g_boff[t] = sh[t] - v;
    if (t == nb - 1) g_offsets[n] = sh[t];
}

__global__ void scan3_kernel(int n) {
    __shared__ int sh[256];
    int b = blockIdx.x, t = threadIdx.x;
    int i = b * 256 + t;
    int v = (i < n) ? g_count[i] : 0;
    sh[t] = v;
    __syncthreads();
    for (int off = 1; off < 256; off <<= 1) {
        int x = (t >= off) ? sh[t - off] : 0;
        __syncthreads();
        sh[t] += x;
        __syncthreads();
    }
    if (i < n) g_offsets[i] = sh[t] - v + g_boff[b];
}

__global__ void dinv_kernel(int n) {
    for (int i = blockIdx.x * blockDim.x + threadIdx.x; i < n;
         i += gridDim.x * blockDim.x)
        g_dinv[i] = rsqrtf((float)(g_count[i] + 1));
}

__global__ void scatter_kernel(const void* __restrict__ edges, int E) {
    for (int i = blockIdx.x * blockDim.x + threadIdx.x; i < E;
         i += gridDim.x * blockDim.x) {
        int s = (int)ld_idx(edges, i);
        int d = (int)ld_idx(edges, (size_t)E + i);
        if (s < 0 || s >= NN || d < 0 || d >= NN) continue;
        int pos = g_offsets[d] + atomicAdd(&g_cursor[d], 1);
        g_csr[pos] = s;
    }
}

// ---------------------------------------------------------------------------
// feats fp32 -> fp16 (rn)
__global__ void convert_feats_kernel(const float4* __restrict__ f4, int n4) {
    __half2* o2 = (__half2*)g_feats_h;
    for (int i = blockIdx.x * blockDim.x + threadIdx.x; i < n4;
         i += gridDim.x * blockDim.x) {
        float4 v = f4[i];
        o2[2 * i]     = __floats2half2_rn(v.x, v.y);
        o2[2 * i + 1] = __floats2half2_rn(v.z, v.w);
    }
}

// All 3 weight transposes fused: W[K,256] -> WT[256,K], fp16 (rn).
__global__ void transpose_all_kernel(const float* __restrict__ W1,
                                     const float* __restrict__ Wg,
                                     const float* __restrict__ Wc) {
    const int T1 = INF * 256;
    const int T2 = (HID + INF) * 256;
    const int T3 = (HID + GCO) * 256;
    int tot = T1 + T2 + T3;
    for (int i = blockIdx.x * blockDim.x + threadIdx.x; i < tot;
         i += gridDim.x * blockDim.x) {
        const float* W; __half* WT; int K, j;
        if (i < T1)           { W = W1; WT = g_W1T; K = INF;       j = i; }
        else if (i < T1 + T2) { W = Wg; WT = g_WgT; K = HID + INF; j = i - T1; }
        else                  { W = Wc; WT = g_WcT; K = HID + GCO; j = i - T1 - T2; }
        int k = j >> 8, n = j & 255;
        WT[(size_t)n * K + k] = __float2half_rn(W[(size_t)k * 256 + n]);
    }
}

// ---------------------------------------------------------------------------
// fp16 mma.sync GEMM: C[M,256] = concat_k(A1[M,K1], A2[M,K2]) @ WT^T
// 2-stage cp.async pipeline, 3 CTAs/SM. Fast-ELU + bias-hoisted epilogue.
__global__ __launch_bounds__(256, 3) void tc_gemm(
    const __half* __restrict__ A1, int K1,
    const __half* __restrict__ A2, int K2,
    const __half* __restrict__ BT,
    const float* __restrict__ bias,
    void* __restrict__ Cv, int ldc, int M, int do_elu, int out_half)
{
    extern __shared__ char smem[];
    const uint32_t sb = smem_u32(smem);
    const int tid = threadIdx.x;
    const int wid = tid >> 5, lid = tid & 31;
    const int wm = wid >> 1, wn = wid & 1;
    const int m0 = blockIdx.y * BM;
    const int n0 = blockIdx.x * BN;
    const int Ktot = K1 + K2;
    const int nT = Ktot / BK;

    const int ldr = tid >> 1;           // 0..127 (tile row)
    const int ldh = (tid & 1) * 16;     // 0 or 16 halves (32B)

    float acc[2][8][4];
#pragma unroll
    for (int i = 0; i < 2; i++)
#pragma unroll
        for (int j = 0; j < 8; j++)
#pragma unroll
            for (int q = 0; q < 4; q++) acc[i][j][q] = 0.f;

    auto load_stage = [&](int t) {
        const int s = t & 1;
        const uint32_t aOff = s * 2 * TILE_B;
        const uint32_t bOff = aOff + TILE_B;
        const int k0 = t * BK;
        const __half* A; int K, kc;
        if (k0 < K1) { A = A1; K = K1; kc = k0; }
        else         { A = A2; K = K2; kc = k0 - K1; }
        const int arow = m0 + ldr;
        const int asz = (arow < M) ? 16 : 0;
        const __half* asrc = A + (size_t)arow * K + kc + ldh;
        const __half* bsrc = BT + (size_t)(n0 + ldr) * Ktot + k0 + ldh;
        const uint32_t adst = sb + aOff + (ldr * LDH + ldh) * 2;
        const uint32_t bdst = sb + bOff + (ldr * LDH + ldh) * 2;
#pragma unroll
        for (int j = 0; j < 2; j++) {
            cp16(adst + j * 16, asrc + j * 8, asz);
            cp16(bdst + j * 16, bsrc + j * 8, 16);
        }
        asm volatile("cp.async.commit_group;" ::: "memory");
    };

    load_stage(0);

    for (int t = 0; t < nT; t++) {
        if (t + 1 < nT) {
            load_stage(t + 1);
            asm volatile("cp.async.wait_group 1;" ::: "memory");
        } else {
            asm volatile("cp.async.wait_group 0;" ::: "memory");
        }
        __syncthreads();

        const int s = t & 1;
        const uint32_t* Au = (const uint32_t*)(smem + s * 2 * TILE_B);
        const uint32_t* Bu = (const uint32_t*)(smem + s * 2 * TILE_B + TILE_B);

        const int g = lid >> 2;
        const int lg = lid & 3;

#pragma unroll
        for (int kk = 0; kk < 2; kk++) {
            const int kU = kk * 8;
            uint32_t a[2][4];
#pragma unroll
            for (int mt = 0; mt < 2; mt++) {
                const int r0 = wm * 32 + mt * 16 + g;
                a[mt][0] = Au[(r0)     * 36 + kU + lg];
                a[mt][1] = Au[(r0 + 8) * 36 + kU + lg];
                a[mt][2] = Au[(r0)     * 36 + kU + lg + 4];
                a[mt][3] = Au[(r0 + 8) * 36 + kU + lg + 4];
            }
#pragma unroll
            for (int nt = 0; nt < 8; nt++) {
                const int c0 = wn * 64 + nt * 8 + g;
                uint32_t b[2];
                b[0] = Bu[c0 * 36 + kU + lg];
                b[1] = Bu[c0 * 36 + kU + lg + 4];
                mma_f16(acc[0][nt], a[0], b);
                mma_f16(acc[1][nt], a[1], b);
            }
        }
        __syncthreads();
    }

    // ---- epilogue: hoisted bias + fast ELU; fp32 or fp16 stores ----
    const int g = lid >> 2;
    const int lg = lid & 3;
    float* Cf = (float*)Cv;
    __half* Ch = (__half*)Cv;

    // hoist 16 bias values (2 per nt), reused across 2 mt x 2 row-offsets
    float bv[8][2];
#pragma unroll
    for (int nt = 0; nt < 8; nt++) {
        const int col = n0 + wn * 64 + nt * 8 + lg * 2;
        bv[nt][0] = bias ? __ldg(&bias[col])     : 0.f;
        bv[nt][1] = bias ? __ldg(&bias[col + 1]) : 0.f;
    }

#pragma unroll
    for (int mt = 0; mt < 2; mt++) {
        const int r0 = m0 + wm * 32 + mt * 16 + g;
#pragma unroll
        for (int nt = 0; nt < 8; nt++) {
            const int col = n0 + wn * 64 + nt * 8 + lg * 2;
            float x0 = acc[mt][nt][0] + bv[nt][0];
            float x1 = acc[mt][nt][1] + bv[nt][1];
            float x2 = acc[mt][nt][2] + bv[nt][0];
            float x3 = acc[mt][nt][3] + bv[nt][1];
            if (do_elu) {
                x0 = elu_fast(x0);
                x1 = elu_fast(x1);
                x2 = elu_fast(x2);
                x3 = elu_fast(x3);
            }
            if (out_half) {
                if (r0 < M)
                    *(__half2*)(Ch + (size_t)r0 * ldc + col) =
                        __floats2half2_rn(x0, x1);
                if (r0 + 8 < M)
                    *(__half2*)(Ch + (size_t)(r0 + 8) * ldc + col) =
                        __floats2half2_rn(x2, x3);
            } else {
                if (r0 < M)
                    *(float2*)(Cf + (size_t)r0 * ldc + col) = make_float2(x0, x1);
                if (r0 + 8 < M)
                    *(float2*)(Cf + (size_t)(r0 + 8) * ldc + col) =
                        make_float2(x2, x3);
            }
        }
    }
}

// ---------------------------------------------------------------------------
// Aggregation over fp16 xw: 8 nodes / 256-thread block, 32 threads per node,
// uint4 (8 halves) per lane, fp32 accumulation, x2-unrolled gather.
__device__ __forceinline__ void h8_fma(float2* acc, uint4 v, float w) {
    const __half2* h = (const __half2*)&v;
#pragma unroll
    for (int j = 0; j < 4; j++) {
        float2 f = __half22float2(h[j]);
        acc[j].x += f.x * w;
        acc[j].y += f.y * w;
    }
}

__global__ __launch_bounds__(256) void agg_kernel(const float* __restrict__ bg,
                                                  int N) {
    const int row = blockIdx.x * 8 + (threadIdx.x >> 5);
    const int t = threadIdx.x & 31;
    if (row >= N) return;
    const uint4* xw4 = (const uint4*)g_xw_h;
    const int cnt = g_count[row];
    const float inv_deg = 1.0f / (float)(cnt + 1);
    const float dinv_r = g_dinv[row];

    float2 acc[4] = {{0.f,0.f},{0.f,0.f},{0.f,0.f},{0.f,0.f}};
    h8_fma(acc, xw4[(size_t)row * 32 + t], inv_deg);

    const int beg = g_offsets[row], end = beg + cnt;
    int e = beg;
    for (; e + 2 <= end; e += 2) {
        int s0 = g_csr[e], s1 = g_csr[e + 1];
        float w0 = dinv_r * __ldg(&g_dinv[s0]);
        float w1 = dinv_r * __ldg(&g_dinv[s1]);
        uint4 x0 = __ldg(&xw4[(size_t)s0 * 32 + t]);
        uint4 x1 = __ldg(&xw4[(size_t)s1 * 32 + t]);
        h8_fma(acc, x0, w0);
        h8_fma(acc, x1, w1);
    }
    if (e < end) {
        int s0 = g_csr[e];
        float w0 = dinv_r * __ldg(&g_dinv[s0]);
        h8_fma(acc, __ldg(&xw4[(size_t)s0 * 32 + t]), w0);
    }

    const float4* bg4 = (const float4*)bg;
    float4 b0 = __ldg(&bg4[t * 2]);
    float4 b1 = __ldg(&bg4[t * 2 + 1]);
    acc[0].x += b0.x; acc[0].y += b0.y;
    acc[1].x += b0.z; acc[1].y += b0.w;
    acc[2].x += b1.x; acc[2].y += b1.y;
    acc[3].x += b1.z; acc[3].y += b1.w;

    uint4 o;
    __half2* oh = (__half2*)&o;
#pragma unroll
    for (int j = 0; j < 4; j++)
        oh[j] = __floats2half2_rn(acc[j].x, acc[j].y);
    ((uint4*)g_gc_h)[(size_t)row * 32 + t] = o;
}

// ---------------------------------------------------------------------------
__global__ void copy_feats_kernel(const float4* __restrict__ feats4,
                                  float4* __restrict__ out4, int N) {
    int tot = N * 32;
    for (int i = blockIdx.x * blockDim.x + threadIdx.x; i < tot;
         i += gridDim.x * blockDim.x) {
        int r = i >> 5, c = i & 31;
        out4[(size_t)r * 96 + 64 + c] = feats4[i];
    }
}

__global__ void copy_tail_kernel(const void* __restrict__ edges,
                                 const void* __restrict__ batch,
                                 float* __restrict__ out, int N, int E,
                                 long long tailMax) {
    size_t base = (size_t)N * (FO + INF);
    long long tot = 2LL * E + N;
    if (tot > tailMax) tot = tailMax;
    for (long long i = blockIdx.x * (long long)blockDim.x + threadIdx.x; i < tot;
         i += (long long)gridDim.x * blockDim.x) {
        long long v = (i < 2LL * E) ? ld_idx(edges, i) : ld_idx(batch, i - 2LL * E);
        out[base + i] = (float)v;
    }
}

// ---------------------------------------------------------------------------
extern "C" void kernel_launch(void* const* d_in, const int* in_sizes, int n_in,
                              void* d_out, int out_size) {
    const float* feats = (const float*)d_in[0];
    const void*  edges = d_in[1];
    const void*  batch = d_in[2];
    const float* W1    = (const float*)d_in[3];
    const float* b1    = (const float*)d_in[4];
    const float* Wg    = (const float*)d_in[5];
    const float* bg    = (const float*)d_in[6];
    const float* Wc    = (const float*)d_in[7];
    const float* bc    = (const float*)d_in[8];
    float* out = (float*)d_out;

    const int N = NN, E = EE;
    const int nBlk = (N + 255) / 256;  // 391

    __half *p_fh, *p_nfh, *p_gch, *p_xwh, *p_w1t, *p_wgt, *p_wct;
    cudaGetSymbolAddress((void**)&p_fh, g_feats_h);
    cudaGetSymbolAddress((void**)&p_nfh, g_nfeats_h);
    cudaGetSymbolAddress((void**)&p_gch, g_gc_h);
    cudaGetSymbolAddress((void**)&p_xwh, g_xw_h);
    cudaGetSymbolAddress((void**)&p_w1t, g_W1T);
    cudaGetSymbolAddress((void**)&p_wgt, g_WgT);
    cudaGetSymbolAddress((void**)&p_wct, g_WcT);

    static cudaStream_t s1 = nullptr;
    static cudaEvent_t evFork = nullptr, evCSR = nullptr, evSide = nullptr,
                       evWT = nullptr;
    if (!s1) {
        cudaFuncSetAttribute(tc_gemm, cudaFuncAttributeMaxDynamicSharedMemorySize,
                             GEMM_SMEM);
        cudaStreamCreateWithFlags(&s1, cudaStreamNonBlocking);
        cudaEventCreateWithFlags(&evFork, cudaEventDisableTiming);
        cudaEventCreateWithFlags(&evCSR, cudaEventDisableTiming);
        cudaEventCreateWithFlags(&evSide, cudaEventDisableTiming);
        cudaEventCreateWithFlags(&evWT, cudaEventDisableTiming);
    }

    // ---- fork side stream ----
    cudaEventRecord(evFork, 0);
    cudaStreamWaitEvent(s1, evFork, 0);

    const int nMT = (N + BM - 1) / BM;  // 782
    dim3 grid(2, nMT);

    // main: feats fp32 -> fp16
    convert_feats_kernel<<<256, 256>>>((const float4*)feats, N * INF / 4);
    // side: all weight transposes (fp16) -- overlaps convert
    transpose_all_kernel<<<256, 256, 0, s1>>>(W1, Wg, Wc);
    cudaEventRecord(evWT, s1);
    // side: CSR prologue
    detect_kernel<<<1, 256, 0, s1>>>((const unsigned int*)edges, 4096);
    zero_kernel<<<256, 256, 0, s1>>>(N);
    hist_kernel<<<512, 256, 0, s1>>>(edges, E);

    // main: GEMM1 -- needs W1T + feats_h
    cudaStreamWaitEvent(0, evWT, 0);
    tc_gemm<<<grid, 256, GEMM_SMEM>>>(p_fh, INF, nullptr, 0, p_w1t, b1,
                                      p_nfh, HID, N, 1, 1);

    // side: rest of CSR chain + output copies
    scan1_kernel<<<nBlk, 256, 0, s1>>>(N);
    scan2_kernel<<<1, 512, 0, s1>>>(nBlk, N);
    scan3_kernel<<<nBlk, 256, 0, s1>>>(N);
    dinv_kernel<<<256, 256, 0, s1>>>(N);
    scatter_kernel<<<512, 256, 0, s1>>>(edges, E);
    cudaEventRecord(evCSR, s1);
    copy_feats_kernel<<<512, 256, 0, s1>>>((const float4*)feats, (float4*)out, N);
    long long tailMax = (long long)out_size - (long long)N * (FO + INF);
    if (tailMax > 0)
        copy_tail_kernel<<<512, 256, 0, s1>>>(edges, batch, out, N, E, tailMax);
    cudaEventRecord(evSide, s1);

    // main: GEMM2 -> xw fp16 (no bias)
    tc_gemm<<<grid, 256, GEMM_SMEM>>>(p_nfh, HID, p_fh, INF, p_wgt, nullptr,
                                      p_xwh, GCO, N, 0, 1);

    // join: aggregation needs CSR + xw; writes gc fp16
    cudaStreamWaitEvent(0, evCSR, 0);
    agg_kernel<<<(N + 7) / 8, 256>>>(bg, N);

    // main: GEMM3 -> out[:, :256] fp32, row stride 384
    tc_gemm<<<grid, 256, GEMM_SMEM>>>(p_nfh, HID, p_gch, GCO, p_wct, bc,
                                      out, FO + INF, N, 1, 0);

    // join side-stream copies before returning
    cudaStreamWaitEvent(0, evSide, 0);
}